// round 1
// baseline (speedup 1.0000x reference)
#include <cuda_runtime.h>
#include <math.h>

// Problem constants
#define BB 32
#define SS 512
#define DD 1024
#define HH 1024
#define OO 1024

// ---------------- scratch (static device memory; no allocations) ----------------
__device__ float g_X0[(size_t)SS * BB * 3 * HH];   // [s][b][z|r|g * H] precomputed x-projections layer 0 (incl bias)
__device__ float g_H1[(size_t)SS * BB * HH];       // [t][b][h] layer-1 hidden per step (input to output projection)
__device__ float g_h0[BB * HH];
__device__ float g_h1[BB * HH];
__device__ float g_z0[BB * HH];
__device__ float g_rh0[BB * HH];
__device__ float g_z1[BB * HH];
__device__ float g_rh1[BB * HH];
__device__ float g_pz1[BB * HH];
__device__ float g_pr1[BB * HH];
__device__ float g_gx1[BB * HH];
__device__ unsigned g_barcnt;

__device__ __forceinline__ float sigmoidf_(float x) { return 1.0f / (1.0f + expf(-x)); }

// ---------------- init: reset barrier counter, load initial hidden states ----------------
__global__ void init_kernel(const float* __restrict__ hs) {
    int i = blockIdx.x * blockDim.x + threadIdx.x;
    if (i == 0) g_barcnt = 0u;
    if (i < BB * HH) {
        int b = i >> 10;
        int h = i & 1023;
        g_h0[i] = hs[b * (2 * HH) + h];
        g_h1[i] = hs[b * (2 * HH) + HH + h];
    }
}

// ---------------- batched GEMM: X0 = input @ [Wxz0;Wxr0;Wxg0].T + [bz0;br0;bg0] ----------------
// M = B*S = 16384 (row m = b*S+s), N = 3072 (gate*1024+j), K = 1024
#define GBM 128
#define GBN 128
#define GBK 8
__global__ void __launch_bounds__(256) pre_gemm_kernel(
    const float* __restrict__ A,
    const float* __restrict__ Wxz, const float* __restrict__ Wxr, const float* __restrict__ Wxg,
    const float* __restrict__ bz, const float* __restrict__ br, const float* __restrict__ bg)
{
    __shared__ __align__(16) float As[GBK][GBM];
    __shared__ __align__(16) float Bs[GBK][GBN];

    int tid = threadIdx.x;
    int row0 = blockIdx.y * GBM;
    int col0 = blockIdx.x * GBN;
    int tr = tid >> 4;   // 0..15
    int tc = tid & 15;   // 0..15

    int gate = col0 >> 10;                 // tiles never straddle gates (1024 % 128 == 0)
    const float* Wg = (gate == 0) ? Wxz : ((gate == 1) ? Wxr : Wxg);
    const float* bias = (gate == 0) ? bz : ((gate == 1) ? br : bg);
    int jbase = col0 & 1023;

    float acc[8][8];
    #pragma unroll
    for (int i = 0; i < 8; i++)
        #pragma unroll
        for (int j = 0; j < 8; j++) acc[i][j] = 0.0f;

    for (int k0 = 0; k0 < DD; k0 += GBK) {
        #pragma unroll
        for (int i = 0; i < 4; i++) {
            int idx = tid + i * 256;
            int r = idx >> 3, c = idx & 7;
            As[c][r] = A[(size_t)(row0 + r) * DD + k0 + c];
        }
        #pragma unroll
        for (int i = 0; i < 4; i++) {
            int idx = tid + i * 256;
            int n = idx >> 3, c = idx & 7;
            Bs[c][n] = Wg[(size_t)(jbase + n) * DD + k0 + c];
        }
        __syncthreads();
        #pragma unroll
        for (int k = 0; k < GBK; k++) {
            float4 a0 = *(const float4*)&As[k][tr * 8];
            float4 a1 = *(const float4*)&As[k][tr * 8 + 4];
            float4 b0 = *(const float4*)&Bs[k][tc * 8];
            float4 b1 = *(const float4*)&Bs[k][tc * 8 + 4];
            float av[8] = {a0.x, a0.y, a0.z, a0.w, a1.x, a1.y, a1.z, a1.w};
            float bv[8] = {b0.x, b0.y, b0.z, b0.w, b1.x, b1.y, b1.z, b1.w};
            #pragma unroll
            for (int i = 0; i < 8; i++)
                #pragma unroll
                for (int j = 0; j < 8; j++)
                    acc[i][j] = fmaf(av[i], bv[j], acc[i][j]);
        }
        __syncthreads();
    }

    #pragma unroll
    for (int i = 0; i < 8; i++) {
        int m = row0 + tr * 8 + i;
        int s = m & 511;
        int b = m >> 9;
        size_t obase = ((size_t)s * BB + b) * (3 * HH) + col0 + tc * 8;
        #pragma unroll
        for (int j = 0; j < 8; j++) {
            g_X0[obase + j] = acc[i][j] + bias[jbase + tc * 8 + j];
        }
    }
}

// ---------------- output projection: out = H1 @ Why.T + by ----------------
__global__ void __launch_bounds__(256) post_gemm_kernel(
    const float* __restrict__ Why, const float* __restrict__ by, float* __restrict__ out)
{
    __shared__ __align__(16) float As[GBK][GBM];
    __shared__ __align__(16) float Bs[GBK][GBN];

    int tid = threadIdx.x;
    int row0 = blockIdx.y * GBM;
    int col0 = blockIdx.x * GBN;
    int tr = tid >> 4;
    int tc = tid & 15;

    float acc[8][8];
    #pragma unroll
    for (int i = 0; i < 8; i++)
        #pragma unroll
        for (int j = 0; j < 8; j++) acc[i][j] = 0.0f;

    for (int k0 = 0; k0 < HH; k0 += GBK) {
        #pragma unroll
        for (int i = 0; i < 4; i++) {
            int idx = tid + i * 256;
            int r = idx >> 3, c = idx & 7;
            As[c][r] = g_H1[(size_t)(row0 + r) * HH + k0 + c];
        }
        #pragma unroll
        for (int i = 0; i < 4; i++) {
            int idx = tid + i * 256;
            int n = idx >> 3, c = idx & 7;
            Bs[c][n] = Why[(size_t)(col0 + n) * HH + k0 + c];
        }
        __syncthreads();
        #pragma unroll
        for (int k = 0; k < GBK; k++) {
            float4 a0 = *(const float4*)&As[k][tr * 8];
            float4 a1 = *(const float4*)&As[k][tr * 8 + 4];
            float4 b0 = *(const float4*)&Bs[k][tc * 8];
            float4 b1 = *(const float4*)&Bs[k][tc * 8 + 4];
            float av[8] = {a0.x, a0.y, a0.z, a0.w, a1.x, a1.y, a1.z, a1.w};
            float bv[8] = {b0.x, b0.y, b0.z, b0.w, b1.x, b1.y, b1.z, b1.w};
            #pragma unroll
            for (int i = 0; i < 8; i++)
                #pragma unroll
                for (int j = 0; j < 8; j++)
                    acc[i][j] = fmaf(av[i], bv[j], acc[i][j]);
        }
        __syncthreads();
    }

    #pragma unroll
    for (int i = 0; i < 8; i++) {
        int m = row0 + tr * 8 + i;   // m = t*32 + b
        int t = m >> 5;
        int b = m & 31;
        size_t obase = ((size_t)b * SS + t) * OO + col0 + tc * 8;
        #pragma unroll
        for (int j = 0; j < 8; j++) {
            out[obase + j] = acc[i][j] + by[col0 + tc * 8 + j];
        }
    }
}

// ---------------- grid barrier (monotonic counter, reset each launch by init_kernel) ----------------
__device__ __forceinline__ void grid_barrier(unsigned target) {
    __syncthreads();
    if (threadIdx.x == 0) {
        __threadfence();                    // release our writes
        atomicAdd(&g_barcnt, 1u);
        unsigned v;
        do {
            asm volatile("ld.acquire.gpu.u32 %0, [%1];" : "=r"(v) : "l"(&g_barcnt) : "memory");
        } while (v < target);
        __threadfence();                    // acquire others' writes
    }
    __syncthreads();
}

// ---------------- warp-level reduction via padded smem transpose ----------------
// acc[b] holds the lane's k-partial for batch b; returns full sum, valid value used by lane==b.
__device__ __forceinline__ float wreduce(const float* acc, float* sredw, int lane) {
    __syncwarp();
    #pragma unroll
    for (int b = 0; b < 32; b++) sredw[b * 33 + lane] = acc[b];
    __syncwarp();
    float v = 0.0f;
    #pragma unroll
    for (int k = 0; k < 32; k++) v += sredw[lane * 33 + k];
    return v;
}

// NW weight rows against the staged activation block xs[32][1024]
template <int NW>
__device__ __forceinline__ void dotN(const float* __restrict__ xs,
                                     const float* __restrict__ w0,
                                     const float* __restrict__ w1,
                                     const float* __restrict__ w2,
                                     float* sredw, int lane, float* out)
{
    float a0[32], a1[32], a2[32];
    #pragma unroll
    for (int b = 0; b < 32; b++) { a0[b] = 0.f; if (NW > 1) a1[b] = 0.f; if (NW > 2) a2[b] = 0.f; }

    #pragma unroll 2
    for (int k = lane; k < HH; k += 32) {
        float ww0 = w0[k];
        float ww1 = (NW > 1) ? w1[k] : 0.f;
        float ww2 = (NW > 2) ? w2[k] : 0.f;
        #pragma unroll
        for (int b = 0; b < 32; b++) {
            float xv = xs[b * HH + k];          // bank == lane -> conflict-free
            a0[b] = fmaf(xv, ww0, a0[b]);
            if (NW > 1) a1[b] = fmaf(xv, ww1, a1[b]);
            if (NW > 2) a2[b] = fmaf(xv, ww2, a2[b]);
        }
    }
    out[0] = wreduce(a0, sredw, lane);
    if (NW > 1) out[1] = wreduce(a1, sredw, lane);
    if (NW > 2) out[2] = wreduce(a2, sredw, lane);
}

__device__ __forceinline__ void stage_x(const float* __restrict__ src, float* __restrict__ xs) {
    const float4* s4 = (const float4*)src;
    float4* d4 = (float4*)xs;
    for (int i = threadIdx.x; i < (BB * HH) / 4; i += 256) d4[i] = s4[i];
    __syncthreads();
}

// ---------------- persistent sequential kernel ----------------
// 5 phases per timestep; grid barrier between phases.
#define SEQ_SMEM_FLOATS (BB * HH + 8 * 32 * 33)
__global__ void __launch_bounds__(256) seq_kernel(
    const float* __restrict__ Whz, const float* __restrict__ Whr, const float* __restrict__ Whg,
    const float* __restrict__ Wxz, const float* __restrict__ Wxr, const float* __restrict__ Wxg,
    const float* __restrict__ bz,  const float* __restrict__ br,  const float* __restrict__ bg,
    int nCTA)
{
    extern __shared__ float sm[];
    float* xs = sm;                          // 32*1024 staged activations
    int tid = threadIdx.x;
    int lane = tid & 31;
    int wid = tid >> 5;
    float* sredw = sm + BB * HH + wid * (32 * 33);

    int gw = blockIdx.x * 8 + wid;
    int nwarps = nCTA * 8;

    const float* Whz0 = Whz;             const float* Whz1 = Whz + (size_t)HH * HH;
    const float* Whr0 = Whr;             const float* Whr1 = Whr + (size_t)HH * HH;
    const float* Whg0 = Whg;             const float* Whg1 = Whg + (size_t)HH * HH;
    const float* Wxz1 = Wxz + (size_t)HH * DD;
    const float* Wxr1 = Wxr + (size_t)HH * DD;
    const float* Wxg1 = Wxg + (size_t)HH * DD;

    unsigned ep = 0;
    int b = lane;   // epilogue batch index

    for (int t = 0; t < SS; t++) {
        size_t x0base = ((size_t)t * BB + b) * (3 * HH);

        // ---- Phase A: layer0 z,r  (x-operand: h0) ----
        ep++; grid_barrier(ep * nCTA);
        stage_x(g_h0, xs);
        for (int j = gw; j < HH; j += nwarps) {
            float v[2];
            dotN<2>(xs, Whz0 + (size_t)j * HH, Whr0 + (size_t)j * HH, nullptr, sredw, lane, v);
            float z = sigmoidf_(g_X0[x0base + j] + v[0]);
            float r = sigmoidf_(g_X0[x0base + HH + j] + v[1]);
            g_z0[b * HH + j] = z;
            g_rh0[b * HH + j] = r * xs[b * HH + j];
        }

        // ---- Phase B: layer0 g + h0 update  (x-operand: r*h0) ----
        ep++; grid_barrier(ep * nCTA);
        stage_x(g_rh0, xs);
        for (int jp = gw; jp < HH / 2; jp += nwarps) {
            int j0 = jp * 2;
            float v[2];
            dotN<2>(xs, Whg0 + (size_t)j0 * HH, Whg0 + (size_t)(j0 + 1) * HH, nullptr, sredw, lane, v);
            #pragma unroll
            for (int q = 0; q < 2; q++) {
                int jj = j0 + q;
                float g = tanhf(g_X0[x0base + 2 * HH + jj] + v[q]);
                float h_old = g_h0[b * HH + jj];
                float z = g_z0[b * HH + jj];
                g_h0[b * HH + jj] = z * h_old + (1.0f - z) * g;
            }
        }

        // ---- Phase C1: layer1 x-parts (x-operand: new h0) ----
        ep++; grid_barrier(ep * nCTA);
        stage_x(g_h0, xs);
        for (int j = gw; j < HH; j += nwarps) {
            float v[3];
            dotN<3>(xs, Wxz1 + (size_t)j * HH, Wxr1 + (size_t)j * HH, Wxg1 + (size_t)j * HH, sredw, lane, v);
            g_pz1[b * HH + j] = v[0] + bz[HH + j];
            g_pr1[b * HH + j] = v[1] + br[HH + j];
            g_gx1[b * HH + j] = v[2] + bg[HH + j];
        }

        // ---- Phase C2: layer1 z,r  (x-operand: h1) ----
        ep++; grid_barrier(ep * nCTA);
        stage_x(g_h1, xs);
        for (int j = gw; j < HH; j += nwarps) {
            float v[2];
            dotN<2>(xs, Whz1 + (size_t)j * HH, Whr1 + (size_t)j * HH, nullptr, sredw, lane, v);
            float z1 = sigmoidf_(g_pz1[b * HH + j] + v[0]);
            float r1 = sigmoidf_(g_pr1[b * HH + j] + v[1]);
            g_z1[b * HH + j] = z1;
            g_rh1[b * HH + j] = r1 * xs[b * HH + j];
        }

        // ---- Phase D: layer1 g + h1 update  (x-operand: r1*h1) ----
        ep++; grid_barrier(ep * nCTA);
        stage_x(g_rh1, xs);
        for (int jp = gw; jp < HH / 2; jp += nwarps) {
            int j0 = jp * 2;
            float v[2];
            dotN<2>(xs, Whg1 + (size_t)j0 * HH, Whg1 + (size_t)(j0 + 1) * HH, nullptr, sredw, lane, v);
            #pragma unroll
            for (int q = 0; q < 2; q++) {
                int jj = j0 + q;
                float g = tanhf(g_gx1[b * HH + jj] + v[q]);
                float h_old = g_h1[b * HH + jj];
                float z = g_z1[b * HH + jj];
                float hn = z * h_old + (1.0f - z) * g;
                g_h1[b * HH + jj] = hn;
                g_H1[((size_t)t * BB + b) * HH + jj] = hn;
            }
        }
    }
}

// ---------------- copy final hidden states into output tail ----------------
__global__ void copy_hidden_kernel(float* __restrict__ out) {
    int i = blockIdx.x * blockDim.x + threadIdx.x;
    if (i < BB * 2 * HH) {
        int b = i >> 11;
        int rem = i & 2047;
        int l = rem >> 10;
        int h = rem & 1023;
        float v = (l == 0) ? g_h0[b * HH + h] : g_h1[b * HH + h];
        out[(size_t)BB * SS * OO + i] = v;
    }
}

// ---------------- launch ----------------
extern "C" void kernel_launch(void* const* d_in, const int* in_sizes, int n_in,
                              void* d_out, int out_size)
{
    const float* input  = (const float*)d_in[0];
    const float* hidden = (const float*)d_in[1];
    const float* Wxz    = (const float*)d_in[2];
    const float* Whz    = (const float*)d_in[3];
    const float* bz     = (const float*)d_in[4];
    const float* Wxr    = (const float*)d_in[5];
    const float* Whr    = (const float*)d_in[6];
    const float* br     = (const float*)d_in[7];
    const float* Wxg    = (const float*)d_in[8];
    const float* Whg    = (const float*)d_in[9];
    const float* bg     = (const float*)d_in[10];
    const float* Why    = (const float*)d_in[11];
    const float* by     = (const float*)d_in[12];
    float* out = (float*)d_out;

    int nSM = 0;
    cudaDeviceGetAttribute(&nSM, cudaDevAttrMultiProcessorCount, 0);
    if (nSM <= 0) nSM = 148;

    size_t seq_smem = (size_t)SEQ_SMEM_FLOATS * sizeof(float);
    cudaFuncSetAttribute(seq_kernel, cudaFuncAttributeMaxDynamicSharedMemorySize, (int)seq_smem);

    init_kernel<<<(BB * HH + 255) / 256, 256>>>(hidden);

    dim3 preGrid((3 * HH) / GBN, (BB * SS) / GBM);
    pre_gemm_kernel<<<preGrid, 256>>>(input, Wxz, Wxr, Wxg, bz, br, bg);

    seq_kernel<<<nSM, 256, seq_smem>>>(Whz, Whr, Whg, Wxz, Wxr, Wxg, bz, br, bg, nSM);

    dim3 postGrid(OO / GBN, (BB * SS) / GBM);
    post_gemm_kernel<<<postGrid, 256>>>(Why, by, out);

    copy_hidden_kernel<<<(BB * 2 * HH + 255) / 256, 256>>>(out);
}

// round 2
// speedup vs baseline: 1.0127x; 1.0127x over previous
#include <cuda_runtime.h>
#include <math.h>

// Problem constants
#define BB 32
#define SS 512
#define DD 1024
#define HH 1024
#define OO 1024

// ---------------- scratch (static device memory; no allocations) ----------------
__device__ float g_X0[(size_t)SS * BB * 3 * HH];   // [s][b][z|r|g * H] precomputed x-projections layer 0 (incl bias)
__device__ float g_H1[(size_t)SS * BB * HH];       // [t][b][h] layer-1 hidden per step (input to output projection)
__device__ float g_h0[BB * HH];
__device__ float g_h1[BB * HH];
__device__ float g_z0[BB * HH];
__device__ float g_rh0[BB * HH];
__device__ float g_z1[BB * HH];
__device__ float g_rh1[BB * HH];
__device__ float g_pz1[BB * HH];
__device__ float g_pr1[BB * HH];
__device__ float g_gx1[BB * HH];
__device__ unsigned g_barcnt;

__device__ __forceinline__ float sigmoidf_(float x) { return 1.0f / (1.0f + expf(-x)); }

// ---------------- init: reset barrier counter, load initial hidden states ----------------
__global__ void init_kernel(const float* __restrict__ hs) {
    int i = blockIdx.x * blockDim.x + threadIdx.x;
    if (i == 0) g_barcnt = 0u;
    if (i < BB * HH) {
        int b = i >> 10;
        int h = i & 1023;
        g_h0[i] = hs[b * (2 * HH) + h];
        g_h1[i] = hs[b * (2 * HH) + HH + h];
    }
}

// ---------------- batched GEMM: X0 = input @ [Wxz0;Wxr0;Wxg0].T + [bz0;br0;bg0] ----------------
// M = B*S = 16384 (row m = b*S+s), N = 3072 (gate*1024+j), K = 1024
#define GBM 128
#define GBN 128
#define GBK 8
__global__ void __launch_bounds__(256) pre_gemm_kernel(
    const float* __restrict__ A,
    const float* __restrict__ Wxz, const float* __restrict__ Wxr, const float* __restrict__ Wxg,
    const float* __restrict__ bz, const float* __restrict__ br, const float* __restrict__ bg)
{
    __shared__ __align__(16) float As[GBK][GBM];
    __shared__ __align__(16) float Bs[GBK][GBN];

    int tid = threadIdx.x;
    int row0 = blockIdx.y * GBM;
    int col0 = blockIdx.x * GBN;
    int tr = tid >> 4;   // 0..15
    int tc = tid & 15;   // 0..15

    int gate = col0 >> 10;                 // tiles never straddle gates (1024 % 128 == 0)
    const float* Wg = (gate == 0) ? Wxz : ((gate == 1) ? Wxr : Wxg);
    const float* bias = (gate == 0) ? bz : ((gate == 1) ? br : bg);
    int jbase = col0 & 1023;

    float acc[8][8];
    #pragma unroll
    for (int i = 0; i < 8; i++)
        #pragma unroll
        for (int j = 0; j < 8; j++) acc[i][j] = 0.0f;

    for (int k0 = 0; k0 < DD; k0 += GBK) {
        #pragma unroll
        for (int i = 0; i < 4; i++) {
            int idx = tid + i * 256;
            int r = idx >> 3, c = idx & 7;
            As[c][r] = A[(size_t)(row0 + r) * DD + k0 + c];
        }
        #pragma unroll
        for (int i = 0; i < 4; i++) {
            int idx = tid + i * 256;
            int n = idx >> 3, c = idx & 7;
            Bs[c][n] = Wg[(size_t)(jbase + n) * DD + k0 + c];
        }
        __syncthreads();
        #pragma unroll
        for (int k = 0; k < GBK; k++) {
            float4 a0 = *(const float4*)&As[k][tr * 8];
            float4 a1 = *(const float4*)&As[k][tr * 8 + 4];
            float4 b0 = *(const float4*)&Bs[k][tc * 8];
            float4 b1 = *(const float4*)&Bs[k][tc * 8 + 4];
            float av[8] = {a0.x, a0.y, a0.z, a0.w, a1.x, a1.y, a1.z, a1.w};
            float bv[8] = {b0.x, b0.y, b0.z, b0.w, b1.x, b1.y, b1.z, b1.w};
            #pragma unroll
            for (int i = 0; i < 8; i++)
                #pragma unroll
                for (int j = 0; j < 8; j++)
                    acc[i][j] = fmaf(av[i], bv[j], acc[i][j]);
        }
        __syncthreads();
    }

    #pragma unroll
    for (int i = 0; i < 8; i++) {
        int m = row0 + tr * 8 + i;
        int s = m & 511;
        int b = m >> 9;
        size_t obase = ((size_t)s * BB + b) * (3 * HH) + col0 + tc * 8;
        #pragma unroll
        for (int j = 0; j < 8; j++) {
            g_X0[obase + j] = acc[i][j] + bias[jbase + tc * 8 + j];
        }
    }
}

// ---------------- output projection: out = H1 @ Why.T + by ----------------
__global__ void __launch_bounds__(256) post_gemm_kernel(
    const float* __restrict__ Why, const float* __restrict__ by, float* __restrict__ out)
{
    __shared__ __align__(16) float As[GBK][GBM];
    __shared__ __align__(16) float Bs[GBK][GBN];

    int tid = threadIdx.x;
    int row0 = blockIdx.y * GBM;
    int col0 = blockIdx.x * GBN;
    int tr = tid >> 4;
    int tc = tid & 15;

    float acc[8][8];
    #pragma unroll
    for (int i = 0; i < 8; i++)
        #pragma unroll
        for (int j = 0; j < 8; j++) acc[i][j] = 0.0f;

    for (int k0 = 0; k0 < HH; k0 += GBK) {
        #pragma unroll
        for (int i = 0; i < 4; i++) {
            int idx = tid + i * 256;
            int r = idx >> 3, c = idx & 7;
            As[c][r] = g_H1[(size_t)(row0 + r) * HH + k0 + c];
        }
        #pragma unroll
        for (int i = 0; i < 4; i++) {
            int idx = tid + i * 256;
            int n = idx >> 3, c = idx & 7;
            Bs[c][n] = Why[(size_t)(col0 + n) * HH + k0 + c];
        }
        __syncthreads();
        #pragma unroll
        for (int k = 0; k < GBK; k++) {
            float4 a0 = *(const float4*)&As[k][tr * 8];
            float4 a1 = *(const float4*)&As[k][tr * 8 + 4];
            float4 b0 = *(const float4*)&Bs[k][tc * 8];
            float4 b1 = *(const float4*)&Bs[k][tc * 8 + 4];
            float av[8] = {a0.x, a0.y, a0.z, a0.w, a1.x, a1.y, a1.z, a1.w};
            float bv[8] = {b0.x, b0.y, b0.z, b0.w, b1.x, b1.y, b1.z, b1.w};
            #pragma unroll
            for (int i = 0; i < 8; i++)
                #pragma unroll
                for (int j = 0; j < 8; j++)
                    acc[i][j] = fmaf(av[i], bv[j], acc[i][j]);
        }
        __syncthreads();
    }

    #pragma unroll
    for (int i = 0; i < 8; i++) {
        int m = row0 + tr * 8 + i;   // m = t*32 + b
        int t = m >> 5;
        int b = m & 31;
        size_t obase = ((size_t)b * SS + t) * OO + col0 + tc * 8;
        #pragma unroll
        for (int j = 0; j < 8; j++) {
            out[obase + j] = acc[i][j] + by[col0 + tc * 8 + j];
        }
    }
}

// ---------------- grid barrier (monotonic counter, reset each launch by init_kernel) ----------------
__device__ __forceinline__ void grid_barrier(unsigned target) {
    __syncthreads();
    if (threadIdx.x == 0) {
        __threadfence();                    // release our writes
        atomicAdd(&g_barcnt, 1u);
        unsigned v;
        do {
            asm volatile("ld.acquire.gpu.u32 %0, [%1];" : "=r"(v) : "l"(&g_barcnt) : "memory");
        } while (v < target);
        __threadfence();                    // acquire others' writes
    }
    __syncthreads();
}

// ---------------- warp-level reduction via padded smem transpose ----------------
// acc[b] holds the lane's k-partial for batch b; returns full sum, valid value used by lane==b.
__device__ __forceinline__ float wreduce(const float* acc, float* sredw, int lane) {
    __syncwarp();
    #pragma unroll
    for (int b = 0; b < 32; b++) sredw[b * 33 + lane] = acc[b];
    __syncwarp();
    float v = 0.0f;
    #pragma unroll
    for (int k = 0; k < 32; k++) v += sredw[lane * 33 + k];
    return v;
}

// NW weight rows against the staged activation block xs[32][1024]
template <int NW>
__device__ __forceinline__ void dotN(const float* __restrict__ xs,
                                     const float* __restrict__ w0,
                                     const float* __restrict__ w1,
                                     const float* __restrict__ w2,
                                     float* sredw, int lane, float* out)
{
    float a0[32], a1[32], a2[32];
    #pragma unroll
    for (int b = 0; b < 32; b++) { a0[b] = 0.f; if (NW > 1) a1[b] = 0.f; if (NW > 2) a2[b] = 0.f; }

    #pragma unroll 2
    for (int k = lane; k < HH; k += 32) {
        float ww0 = w0[k];
        float ww1 = (NW > 1) ? w1[k] : 0.f;
        float ww2 = (NW > 2) ? w2[k] : 0.f;
        #pragma unroll
        for (int b = 0; b < 32; b++) {
            float xv = xs[b * HH + k];          // bank == lane -> conflict-free
            a0[b] = fmaf(xv, ww0, a0[b]);
            if (NW > 1) a1[b] = fmaf(xv, ww1, a1[b]);
            if (NW > 2) a2[b] = fmaf(xv, ww2, a2[b]);
        }
    }
    out[0] = wreduce(a0, sredw, lane);
    if (NW > 1) out[1] = wreduce(a1, sredw, lane);
    if (NW > 2) out[2] = wreduce(a2, sredw, lane);
}

__device__ __forceinline__ void stage_x(const float* __restrict__ src, float* __restrict__ xs) {
    const float4* s4 = (const float4*)src;
    float4* d4 = (float4*)xs;
    for (int i = threadIdx.x; i < (BB * HH) / 4; i += 256) d4[i] = s4[i];
    __syncthreads();
}

// ---------------- persistent sequential kernel ----------------
// 5 phases per timestep; grid barrier between phases.
#define SEQ_SMEM_FLOATS (BB * HH + 8 * 32 * 33)
__global__ void __launch_bounds__(256) seq_kernel(
    const float* __restrict__ Whz, const float* __restrict__ Whr, const float* __restrict__ Whg,
    const float* __restrict__ Wxz, const float* __restrict__ Wxr, const float* __restrict__ Wxg,
    const float* __restrict__ bz,  const float* __restrict__ br,  const float* __restrict__ bg,
    int nCTA)
{
    extern __shared__ float sm[];
    float* xs = sm;                          // 32*1024 staged activations
    int tid = threadIdx.x;
    int lane = tid & 31;
    int wid = tid >> 5;
    float* sredw = sm + BB * HH + wid * (32 * 33);

    int gw = blockIdx.x * 8 + wid;
    int nwarps = nCTA * 8;

    const float* Whz0 = Whz;             const float* Whz1 = Whz + (size_t)HH * HH;
    const float* Whr0 = Whr;             const float* Whr1 = Whr + (size_t)HH * HH;
    const float* Whg0 = Whg;             const float* Whg1 = Whg + (size_t)HH * HH;
    const float* Wxz1 = Wxz + (size_t)HH * DD;
    const float* Wxr1 = Wxr + (size_t)HH * DD;
    const float* Wxg1 = Wxg + (size_t)HH * DD;

    unsigned ep = 0;
    int b = lane;   // epilogue batch index

    for (int t = 0; t < SS; t++) {
        size_t x0base = ((size_t)t * BB + b) * (3 * HH);

        // ---- Phase A: layer0 z,r  (x-operand: h0) ----
        ep++; grid_barrier(ep * nCTA);
        stage_x(g_h0, xs);
        for (int j = gw; j < HH; j += nwarps) {
            float v[2];
            dotN<2>(xs, Whz0 + (size_t)j * HH, Whr0 + (size_t)j * HH, nullptr, sredw, lane, v);
            float z = sigmoidf_(g_X0[x0base + j] + v[0]);
            float r = sigmoidf_(g_X0[x0base + HH + j] + v[1]);
            g_z0[b * HH + j] = z;
            g_rh0[b * HH + j] = r * xs[b * HH + j];
        }

        // ---- Phase B: layer0 g + h0 update  (x-operand: r*h0) ----
        ep++; grid_barrier(ep * nCTA);
        stage_x(g_rh0, xs);
        for (int jp = gw; jp < HH / 2; jp += nwarps) {
            int j0 = jp * 2;
            float v[2];
            dotN<2>(xs, Whg0 + (size_t)j0 * HH, Whg0 + (size_t)(j0 + 1) * HH, nullptr, sredw, lane, v);
            #pragma unroll
            for (int q = 0; q < 2; q++) {
                int jj = j0 + q;
                float g = tanhf(g_X0[x0base + 2 * HH + jj] + v[q]);
                float h_old = g_h0[b * HH + jj];
                float z = g_z0[b * HH + jj];
                g_h0[b * HH + jj] = z * h_old + (1.0f - z) * g;
            }
        }

        // ---- Phase C1: layer1 x-parts (x-operand: new h0) ----
        ep++; grid_barrier(ep * nCTA);
        stage_x(g_h0, xs);
        for (int j = gw; j < HH; j += nwarps) {
            float v[3];
            dotN<3>(xs, Wxz1 + (size_t)j * HH, Wxr1 + (size_t)j * HH, Wxg1 + (size_t)j * HH, sredw, lane, v);
            g_pz1[b * HH + j] = v[0] + bz[HH + j];
            g_pr1[b * HH + j] = v[1] + br[HH + j];
            g_gx1[b * HH + j] = v[2] + bg[HH + j];
        }

        // ---- Phase C2: layer1 z,r  (x-operand: h1) ----
        ep++; grid_barrier(ep * nCTA);
        stage_x(g_h1, xs);
        for (int j = gw; j < HH; j += nwarps) {
            float v[2];
            dotN<2>(xs, Whz1 + (size_t)j * HH, Whr1 + (size_t)j * HH, nullptr, sredw, lane, v);
            float z1 = sigmoidf_(g_pz1[b * HH + j] + v[0]);
            float r1 = sigmoidf_(g_pr1[b * HH + j] + v[1]);
            g_z1[b * HH + j] = z1;
            g_rh1[b * HH + j] = r1 * xs[b * HH + j];
        }

        // ---- Phase D: layer1 g + h1 update  (x-operand: r1*h1) ----
        ep++; grid_barrier(ep * nCTA);
        stage_x(g_rh1, xs);
        for (int jp = gw; jp < HH / 2; jp += nwarps) {
            int j0 = jp * 2;
            float v[2];
            dotN<2>(xs, Whg1 + (size_t)j0 * HH, Whg1 + (size_t)(j0 + 1) * HH, nullptr, sredw, lane, v);
            #pragma unroll
            for (int q = 0; q < 2; q++) {
                int jj = j0 + q;
                float g = tanhf(g_gx1[b * HH + jj] + v[q]);
                float h_old = g_h1[b * HH + jj];
                float z = g_z1[b * HH + jj];
                float hn = z * h_old + (1.0f - z) * g;
                g_h1[b * HH + jj] = hn;
                g_H1[((size_t)t * BB + b) * HH + jj] = hn;
            }
        }
    }
}

// ---------------- copy final hidden states into output tail ----------------
__global__ void copy_hidden_kernel(float* __restrict__ out) {
    int i = blockIdx.x * blockDim.x + threadIdx.x;
    if (i < BB * 2 * HH) {
        int b = i >> 11;
        int rem = i & 2047;
        int l = rem >> 10;
        int h = rem & 1023;
        float v = (l == 0) ? g_h0[b * HH + h] : g_h1[b * HH + h];
        out[(size_t)BB * SS * OO + i] = v;
    }
}

// ---------------- launch ----------------
extern "C" void kernel_launch(void* const* d_in, const int* in_sizes, int n_in,
                              void* d_out, int out_size)
{
    const float* input  = (const float*)d_in[0];
    const float* hidden = (const float*)d_in[1];
    const float* Wxz    = (const float*)d_in[2];
    const float* Whz    = (const float*)d_in[3];
    const float* bz     = (const float*)d_in[4];
    const float* Wxr    = (const float*)d_in[5];
    const float* Whr    = (const float*)d_in[6];
    const float* br     = (const float*)d_in[7];
    const float* Wxg    = (const float*)d_in[8];
    const float* Whg    = (const float*)d_in[9];
    const float* bg     = (const float*)d_in[10];
    const float* Why    = (const float*)d_in[11];
    const float* by     = (const float*)d_in[12];
    float* out = (float*)d_out;

    int nSM = 0;
    cudaDeviceGetAttribute(&nSM, cudaDevAttrMultiProcessorCount, 0);
    if (nSM <= 0) nSM = 148;

    size_t seq_smem = (size_t)SEQ_SMEM_FLOATS * sizeof(float);
    cudaFuncSetAttribute(seq_kernel, cudaFuncAttributeMaxDynamicSharedMemorySize, (int)seq_smem);

    init_kernel<<<(BB * HH + 255) / 256, 256>>>(hidden);

    dim3 preGrid((3 * HH) / GBN, (BB * SS) / GBM);
    pre_gemm_kernel<<<preGrid, 256>>>(input, Wxz, Wxr, Wxg, bz, br, bg);

    seq_kernel<<<nSM, 256, seq_smem>>>(Whz, Whr, Whg, Wxz, Wxr, Wxg, bz, br, bg, nSM);

    dim3 postGrid(OO / GBN, (BB * SS) / GBM);
    post_gemm_kernel<<<postGrid, 256>>>(Why, by, out);

    copy_hidden_kernel<<<(BB * 2 * HH + 255) / 256, 256>>>(out);
}